// round 8
// baseline (speedup 1.0000x reference)
#include <cuda_runtime.h>
#include <cstdint>

#define BATCH_MAX 16384
#define XDIM 64
#define ADIM 16
#define NCON 8
#define N_ITERS 100
#define POW_ITERS 16
#define EPSC 0.05f   /* 1/(2*PEN) */

typedef unsigned long long ull;

// ---------------- packed f32x2 helpers (sm_103a FFMA2) ----------------
__device__ __forceinline__ ull ffma2(ull a, ull b, ull c) {
    ull d;
    asm("fma.rn.f32x2 %0, %1, %2, %3;" : "=l"(d) : "l"(a), "l"(b), "l"(c));
    return d;
}
__device__ __forceinline__ float hadd2(ull p) {
    unsigned lo, hi;
    asm("mov.b64 {%0, %1}, %2;" : "=r"(lo), "=r"(hi) : "l"(p));
    return __uint_as_float(lo) + __uint_as_float(hi);
}
__device__ __forceinline__ ull pack2(float a, float b) {
    ull d;
    asm("mov.b64 %0, {%1, %2};" : "=l"(d)
        : "r"(__float_as_uint(a)), "r"(__float_as_uint(b)));
    return d;
}
__device__ __forceinline__ float dot8p(const ull* Sr, const ull* yp) {
    ull acc = ffma2(Sr[0], yp[0], 0ULL);
    acc = ffma2(Sr[1], yp[1], acc);
    acc = ffma2(Sr[2], yp[2], acc);
    acc = ffma2(Sr[3], yp[3], acc);
    return hadd2(acc);
}

// ---------------- cp.async helpers ----------------
__device__ __forceinline__ void cp_async16(void* smem_ptr, const void* gptr) {
    uint32_t a = (uint32_t)__cvta_generic_to_shared(smem_ptr);
    asm volatile("cp.async.cg.shared.global [%0], [%1], 16;" :: "r"(a), "l"(gptr));
}
#define CP_COMMIT() asm volatile("cp.async.commit_group;")
#define CP_WAIT(n)  asm volatile("cp.async.wait_group %0;" :: "n"(n))

// ---------------- scratch (static device globals; no runtime alloc) ----------------
__device__ float g_Y [BATCH_MAX * 512];   // Qc_m x  (flattened r = m*64+i)
__device__ float g_S [BATCH_MAX * 64];    // S = 0.5 Lg Lg^T  (8x8)
__device__ float g_q [BATCH_MAX * 8];     // dual linear term (top half; bottom == 0)
__device__ float g_Lg[BATCH_MAX * 128];   // Lg_h (8x16)

// =====================================================================
// Kernel 1: unchanged (43us; parked until k2 profile lands).
// =====================================================================
#define K1_XS_BYTES  (16 * 129 * 16)
#define K1_WK_BYTES  (64 * 64 * 4)
#define K1_BUF_BYTES (32 * 129 * 4)
#define K1_SMEM (K1_XS_BYTES + K1_WK_BYTES + K1_BUF_BYTES)

__global__ __launch_bounds__(128) void k1_gemm(const float* __restrict__ X,
                                               const float* __restrict__ W)
{
    extern __shared__ char sm_raw[];
    float4 (*Xs4)[129] = (float4(*)[129])sm_raw;
    float  (*Wk)[64]   = (float(*)[64])(sm_raw + K1_XS_BYTES);
    float  (*buf)[129] = (float(*)[129])(sm_raw + K1_XS_BYTES + K1_WK_BYTES);

    const int t  = threadIdx.x;
    const int m0 = blockIdx.x * 128;
    const int n0 = blockIdx.y * 64;
    const int kq = t & 15, rg = t >> 4;

    const float4* X4 = (const float4*)X;
    const float4* W4 = (const float4*)W;
    #pragma unroll
    for (int it = 0; it < 16; it++) {
        int row = it * 8 + rg;
        Xs4[kq][row] = X4[(size_t)(m0 + row) * 16 + kq];
    }
    #pragma unroll
    for (int it = 0; it < 8; it++) {
        int n = it * 8 + rg;
        *(float4*)&Wk[n][kq * 4] = W4[(size_t)(n0 + n) * 16 + kq];
    }
    __syncthreads();

    const int lane = t & 31, w = t >> 5;
    const int m = w * 32 + lane;

    #pragma unroll 1
    for (int pass = 0; pass < 2; pass++) {
        ull acc2[32];
        #pragma unroll
        for (int n = 0; n < 32; n++) acc2[n] = 0ULL;

        const float (*Wp)[64] = Wk + pass * 32;
        #pragma unroll 4
        for (int kq2 = 0; kq2 < 16; kq2++) {
            ulonglong2 xq = *(const ulonglong2*)&Xs4[kq2][m];
            #pragma unroll
            for (int n = 0; n < 32; n++) {
                ulonglong2 wq = *(const ulonglong2*)&Wp[n][kq2 * 4];
                acc2[n] = ffma2(wq.x, xq.x, acc2[n]);
                acc2[n] = ffma2(wq.y, xq.y, acc2[n]);
            }
        }

        #pragma unroll
        for (int n = 0; n < 32; n++) buf[n][m] = hadd2(acc2[n]);
        __syncthreads();
        {
            int n4 = t & 7, mg = t >> 3;
            #pragma unroll
            for (int s = 0; s < 8; s++) {
                int mr = s * 16 + mg;
                float4 o = make_float4(buf[n4 * 4 + 0][mr], buf[n4 * 4 + 1][mr],
                                       buf[n4 * 4 + 2][mr], buf[n4 * 4 + 3][mr]);
                ((float4*)g_Y)[(size_t)(m0 + mr) * 128 + n0 / 4 + pass * 8 + n4] = o;
            }
        }
        __syncthreads();
    }
}

// =====================================================================
// Kernel 2: identical logic to R6; batch-offset parameter enables 4
// quarter-batch launches (moves ncu capture window onto k2).
// =====================================================================
#define GS_STRIDE 68

__global__ __launch_bounds__(128) void k2_setup(
    const float* __restrict__ Xg, const float* __restrict__ Ag,
    const float* __restrict__ Bg, const float* __restrict__ ccg,
    const float* __restrict__ dcg, const float* __restrict__ adg,
    int b0)
{
    __shared__ float xs [4][64];
    __shared__ float zs [4][64];
    __shared__ float gsm[4][NCON * GS_STRIDE];  // gradc
    __shared__ float stg[4][2 * 544];           // A double-stage; later B[64][16]
    __shared__ float Lgs[4][128];
    __shared__ float ccs[512];

    const int tid = threadIdx.x;
    const int w = tid >> 5, lane = tid & 31;
    const int b = b0 + blockIdx.x * 4 + w;

    for (int idx = tid; idx < 512; idx += 128) ccs[idx] = ccg[idx];

    if (lane < 16)
        *(float4*)&xs[w][lane * 4] = *(const float4*)(Xg + (size_t)b * 64 + lane * 4);

    const float4* A4 = (const float4*)(Ag + (size_t)b * 4096);

    #pragma unroll
    for (int c = 0; c < 2; c++) {
        #pragma unroll
        for (int j = 0; j < 4; j++) {
            int p = j * 32 + lane;
            cp_async16(&stg[w][c * 544 + (p >> 4) * GS_STRIDE + (p & 15) * 4],
                       A4 + c * 128 + p);
        }
        CP_COMMIT();
    }
    __syncthreads();

    // ---- z = A x, software-pipelined ----
    {
        const int r = lane & 7, seg = lane >> 3;
        #pragma unroll
        for (int ch = 0; ch < 8; ch++) {
            if (ch < 7) { CP_WAIT(1); } else { CP_WAIT(0); }
            __syncwarp();
            const float* st = &stg[w][(ch & 1) * 544];
            float acc = 0.f;
            #pragma unroll
            for (int j = 0; j < 4; j++) {
                float4 av = *(const float4*)&st[r * GS_STRIDE + seg * 16 + j * 4];
                float4 xv = *(const float4*)&xs[w][seg * 16 + j * 4];
                acc = fmaf(av.x, xv.x, acc);
                acc = fmaf(av.y, xv.y, acc);
                acc = fmaf(av.z, xv.z, acc);
                acc = fmaf(av.w, xv.w, acc);
            }
            acc += __shfl_xor_sync(0xffffffffu, acc, 8);
            acc += __shfl_xor_sync(0xffffffffu, acc, 16);
            if (seg == 0) zs[w][ch * 8 + r] = acc;
            __syncwarp();
            if (ch + 2 < 8) {
                #pragma unroll
                for (int j = 0; j < 4; j++) {
                    int p = j * 32 + lane;
                    cp_async16(&stg[w][(ch & 1) * 544 + (p >> 4) * GS_STRIDE + (p & 15) * 4],
                               A4 + (ch + 2) * 128 + p);
                }
                CP_COMMIT();
            }
        }
    }

    // ---- B tile -> stg (A stage retired) ----
    {
        const float* Bb = Bg + (size_t)b * 1024;
        #pragma unroll
        for (int it = 0; it < 8; it++) {
            int idx = it * 128 + lane * 4;
            cp_async16(&stg[w][idx], Bb + idx);
        }
        CP_COMMIT();
    }

    // ---- gradc = Y + cc (overlaps with B cp.async) ----
    {
        const float* Yb = g_Y + (size_t)b * 512;
        #pragma unroll
        for (int it = 0; it < 4; it++) {
            int idx = it * 128 + lane * 4;
            int m = idx >> 6, i = idx & 63;
            float4 yv = *(const float4*)(Yb + idx);
            yv.x += ccs[idx + 0]; yv.y += ccs[idx + 1];
            yv.z += ccs[idx + 2]; yv.w += ccs[idx + 3];
            *(float4*)&gsm[w][m * GS_STRIDE + i] = yv;
        }
    }
    __syncwarp();

    float sa[NCON], sb[NCON], sc[NCON];
    {
        int i1 = lane, i2 = lane + 32;
        float x1 = xs[w][i1], x2 = xs[w][i2];
        float z1 = zs[w][i1], z2 = zs[w][i2];
        #pragma unroll
        for (int m = 0; m < NCON; m++) {
            float ga = gsm[w][m * GS_STRIDE + i1], gb2 = gsm[w][m * GS_STRIDE + i2];
            float ca = ccs[m * 64 + i1], cb = ccs[m * 64 + i2];
            sa[m] = fmaf(x2, gb2, x1 * ga);
            sb[m] = fmaf(x2, cb, x1 * ca);
            sc[m] = fmaf(z2, gb2, z1 * ga);
        }
    }
    #pragma unroll
    for (int off = 16; off; off >>= 1) {
        #pragma unroll
        for (int m = 0; m < NCON; m++) {
            sa[m] += __shfl_xor_sync(0xffffffffu, sa[m], off);
            sb[m] += __shfl_xor_sync(0xffffffffu, sb[m], off);
            sc[m] += __shfl_xor_sync(0xffffffffu, sc[m], off);
        }
    }

    CP_WAIT(0);
    __syncwarp();

    // Lg[m][a] = -sum_i gradc[m][i] * B[i][a]
    {
        int m = lane >> 2, aq = lane & 3;
        float4 acc = make_float4(0.f, 0.f, 0.f, 0.f);
        const float4* B4 = (const float4*)&stg[w][0];
        #pragma unroll
        for (int i = 0; i < 64; i++) {
            float gv = gsm[w][m * GS_STRIDE + i];
            float4 bv = B4[i * 4 + aq];
            acc.x = fmaf(gv, bv.x, acc.x);
            acc.y = fmaf(gv, bv.y, acc.y);
            acc.z = fmaf(gv, bv.z, acc.z);
            acc.w = fmaf(gv, bv.w, acc.w);
        }
        acc.x = -acc.x; acc.y = -acc.y; acc.z = -acc.z; acc.w = -acc.w;
        *(float4*)&Lgs[w][m * 16 + aq * 4] = acc;
        *(float4*)(g_Lg + (size_t)b * 128 + m * 16 + aq * 4) = acc;
    }
    __syncwarp();

    if (lane < NCON) {
        int m = lane;
        float g    = 0.5f * sa[m] + 0.5f * sb[m] - dcg[m];
        float bvec = sc[m] + g;
        float qm = bvec;
        const float* ad = adg + (size_t)b * 16;
        #pragma unroll
        for (int a = 0; a < 16; a++) qm = fmaf(-Lgs[w][m * 16 + a], ad[a], qm);
        g_q[(size_t)b * 8 + m] = qm;
    }

    #pragma unroll
    for (int e = 0; e < 2; e++) {
        int idx = lane + e * 32;
        int r = idx >> 3, cI = idx & 7;
        float s = 0.f;
        #pragma unroll
        for (int a = 0; a < 16; a++) s = fmaf(Lgs[w][r * 16 + a], Lgs[w][cI * 16 + a], s);
        g_S[(size_t)b * 64 + idx] = 0.5f * s;
    }
}

// =====================================================================
// Kernel 3: thread per element.  POW 16 + FISTA 100 (L inflation 1.01).
// =====================================================================
__global__ __launch_bounds__(128) void k3_fista(const float* __restrict__ adg,
                                                float* __restrict__ out, int batch)
{
    int b = blockIdx.x * 128 + threadIdx.x;
    if (b >= batch) return;

    ull Sp[32];
    {
        const ulonglong2* S2 = (const ulonglong2*)(g_S + (size_t)b * 64);
        #pragma unroll
        for (int i = 0; i < 16; i++) {
            ulonglong2 v = S2[i];
            Sp[2 * i] = v.x; Sp[2 * i + 1] = v.y;
        }
    }
    float q[8];
    {
        const float4* q4 = (const float4*)(g_q + (size_t)b * 8);
        float4 a0 = q4[0], a1 = q4[1];
        q[0] = a0.x; q[1] = a0.y; q[2] = a0.z; q[3] = a0.w;
        q[4] = a1.x; q[5] = a1.y; q[6] = a1.z; q[7] = a1.w;
    }

    float v[8];
    #pragma unroll
    for (int k = 0; k < 8; k++) v[k] = 1.0f + 0.0625f * (float)k;
    #pragma unroll 1
    for (int it = 0; it < POW_ITERS; it++) {
        ull vp[4];
        #pragma unroll
        for (int j = 0; j < 4; j++) vp[j] = pack2(v[2 * j], v[2 * j + 1]);
        float wv[8];
        #pragma unroll
        for (int k = 0; k < 8; k++) wv[k] = dot8p(Sp + 4 * k, vp);
        float ss = 1e-30f;
        #pragma unroll
        for (int k = 0; k < 8; k++) ss = fmaf(wv[k], wv[k], ss);
        float inv = rsqrtf(ss);
        #pragma unroll
        for (int k = 0; k < 8; k++) v[k] = wv[k] * inv;
    }
    float num = 0.f, den = 1e-30f;
    {
        ull vp[4];
        #pragma unroll
        for (int j = 0; j < 4; j++) vp[j] = pack2(v[2 * j], v[2 * j + 1]);
        #pragma unroll
        for (int k = 0; k < 8; k++) {
            num = fmaf(v[k], dot8p(Sp + 4 * k, vp), num);
            den = fmaf(v[k], v[k], den);
        }
    }
    float mu = fmaxf(num / den, 0.f);
    float lamMax = EPSC + 0.5f * (mu + sqrtf(fmaf(mu, mu, 4.f * EPSC * EPSC)));
    float L = lamMax * 1.01f + 1e-6f;
    float t = 1.0f / L;

    float lam[16], y[16];
    #pragma unroll
    for (int k = 0; k < 16; k++) { lam[k] = 0.f; y[k] = 0.f; }
    float tk = 1.0f;
    #pragma unroll 1
    for (int it = 0; it < N_ITERS; it++) {
        ull yp[4];
        #pragma unroll
        for (int j = 0; j < 4; j++) yp[j] = pack2(y[2 * j], y[2 * j + 1]);
        float wv[8];
        #pragma unroll
        for (int k = 0; k < 8; k++) wv[k] = dot8p(Sp + 4 * k, yp);
        float tk1 = 0.5f * (1.0f + sqrtf(fmaf(4.0f * tk, tk, 1.0f)));
        float beta = (tk - 1.0f) / tk1;
        #pragma unroll
        for (int k = 0; k < 8; k++) {
            float e  = EPSC * (y[k] + y[k + 8]);
            float gt = wv[k] + e - q[k];
            float lt = fmaxf(fmaf(-t, gt, y[k]), 0.f);
            float lb = fmaxf(fmaf(-t, e, y[k + 8]), 0.f);
            y[k]     = fmaf(beta, lt - lam[k], lt);
            y[k + 8] = fmaf(beta, lb - lam[k + 8], lb);
            lam[k] = lt; lam[k + 8] = lb;
        }
        tk = tk1;
    }

    float a[16];
    {
        const float4* ad4 = (const float4*)(adg + (size_t)b * 16);
        #pragma unroll
        for (int i = 0; i < 4; i++) {
            float4 t4 = ad4[i];
            a[i * 4 + 0] = t4.x; a[i * 4 + 1] = t4.y; a[i * 4 + 2] = t4.z; a[i * 4 + 3] = t4.w;
        }
        const float* Lgb = g_Lg + (size_t)b * 128;
        #pragma unroll
        for (int m = 0; m < 8; m++) {
            float lm = 0.5f * lam[m];
            #pragma unroll
            for (int j = 0; j < 16; j++) a[j] = fmaf(lm, Lgb[m * 16 + j], a[j]);
        }
    }
    float4* o4 = (float4*)(out + (size_t)b * 16);
    #pragma unroll
    for (int i = 0; i < 4; i++)
        o4[i] = make_float4(a[i * 4 + 0], a[i * 4 + 1], a[i * 4 + 2], a[i * 4 + 3]);
}

// =====================================================================
extern "C" void kernel_launch(void* const* d_in, const int* in_sizes, int n_in,
                              void* d_out, int out_size)
{
    const float* a_des = (const float*)d_in[0];
    const float* x     = (const float*)d_in[1];
    const float* A     = (const float*)d_in[2];
    const float* B     = (const float*)d_in[3];
    const float* Qc    = (const float*)d_in[4];
    const float* cc    = (const float*)d_in[5];
    const float* dc    = (const float*)d_in[6];
    const int batch = in_sizes[0] / ADIM;   // 16384

    cudaFuncSetAttribute(k1_gemm, cudaFuncAttributeMaxDynamicSharedMemorySize, K1_SMEM);

    dim3 g1(batch / 128, 512 / 64);
    k1_gemm<<<g1, 128, K1_SMEM>>>(x, Qc);

    // k2 in 4 quarter-batch launches: shifts the ncu -s 5 -c 1 capture
    // window onto k2 and exposes k2's duration via launch accounting.
    const int quarter = batch / 4;              // elements per launch
    for (int qi = 0; qi < 4; qi++)
        k2_setup<<<quarter / 4, 128>>>(x, A, B, cc, dc, a_des, qi * quarter);

    k3_fista<<<(batch + 127) / 128, 128>>>(a_des, (float*)d_out, batch);
}

// round 9
// speedup vs baseline: 1.1522x; 1.1522x over previous
#include <cuda_runtime.h>
#include <cstdint>

#define BATCH_MAX 16384
#define XDIM 64
#define ADIM 16
#define NCON 8
#define N_ITERS 100
#define POW_ITERS 16
#define EPSC 0.05f   /* 1/(2*PEN) */

typedef unsigned long long ull;

// ---------------- packed f32x2 helpers (sm_103a FFMA2) ----------------
__device__ __forceinline__ ull ffma2(ull a, ull b, ull c) {
    ull d;
    asm("fma.rn.f32x2 %0, %1, %2, %3;" : "=l"(d) : "l"(a), "l"(b), "l"(c));
    return d;
}
__device__ __forceinline__ float hadd2(ull p) {
    unsigned lo, hi;
    asm("mov.b64 {%0, %1}, %2;" : "=r"(lo), "=r"(hi) : "l"(p));
    return __uint_as_float(lo) + __uint_as_float(hi);
}
__device__ __forceinline__ ull pack2(float a, float b) {
    ull d;
    asm("mov.b64 %0, {%1, %2};" : "=l"(d)
        : "r"(__float_as_uint(a)), "r"(__float_as_uint(b)));
    return d;
}
__device__ __forceinline__ float dot8p(const ull* Sr, const ull* yp) {
    ull acc = ffma2(Sr[0], yp[0], 0ULL);
    acc = ffma2(Sr[1], yp[1], acc);
    acc = ffma2(Sr[2], yp[2], acc);
    acc = ffma2(Sr[3], yp[3], acc);
    return hadd2(acc);
}

// ---------------- cp.async helpers ----------------
__device__ __forceinline__ void cp_async16(void* smem_ptr, const void* gptr) {
    uint32_t a = (uint32_t)__cvta_generic_to_shared(smem_ptr);
    asm volatile("cp.async.cg.shared.global [%0], [%1], 16;" :: "r"(a), "l"(gptr));
}
#define CP_COMMIT() asm volatile("cp.async.commit_group;")
#define CP_WAIT(n)  asm volatile("cp.async.wait_group %0;" :: "n"(n))

// ---------------- scratch (static device globals; no runtime alloc) ----------------
__device__ float g_Y [BATCH_MAX * 512];   // Qc_m x  (flattened r = m*64+i)
__device__ float g_S [BATCH_MAX * 64];    // S = 0.5 Lg Lg^T  (8x8)
__device__ float g_q [BATCH_MAX * 8];     // dual linear term (top half; bottom == 0)
__device__ float g_Lg[BATCH_MAX * 128];   // Lg_h (8x16)

// =====================================================================
// Kernel 1: unchanged (43us; frozen).
// =====================================================================
#define K1_XS_BYTES  (16 * 129 * 16)
#define K1_WK_BYTES  (64 * 64 * 4)
#define K1_BUF_BYTES (32 * 129 * 4)
#define K1_SMEM (K1_XS_BYTES + K1_WK_BYTES + K1_BUF_BYTES)

__global__ __launch_bounds__(128) void k1_gemm(const float* __restrict__ X,
                                               const float* __restrict__ W)
{
    extern __shared__ char sm_raw[];
    float4 (*Xs4)[129] = (float4(*)[129])sm_raw;
    float  (*Wk)[64]   = (float(*)[64])(sm_raw + K1_XS_BYTES);
    float  (*buf)[129] = (float(*)[129])(sm_raw + K1_XS_BYTES + K1_WK_BYTES);

    const int t  = threadIdx.x;
    const int m0 = blockIdx.x * 128;
    const int n0 = blockIdx.y * 64;
    const int kq = t & 15, rg = t >> 4;

    const float4* X4 = (const float4*)X;
    const float4* W4 = (const float4*)W;
    #pragma unroll
    for (int it = 0; it < 16; it++) {
        int row = it * 8 + rg;
        Xs4[kq][row] = X4[(size_t)(m0 + row) * 16 + kq];
    }
    #pragma unroll
    for (int it = 0; it < 8; it++) {
        int n = it * 8 + rg;
        *(float4*)&Wk[n][kq * 4] = W4[(size_t)(n0 + n) * 16 + kq];
    }
    __syncthreads();

    const int lane = t & 31, w = t >> 5;
    const int m = w * 32 + lane;

    #pragma unroll 1
    for (int pass = 0; pass < 2; pass++) {
        ull acc2[32];
        #pragma unroll
        for (int n = 0; n < 32; n++) acc2[n] = 0ULL;

        const float (*Wp)[64] = Wk + pass * 32;
        #pragma unroll 4
        for (int kq2 = 0; kq2 < 16; kq2++) {
            ulonglong2 xq = *(const ulonglong2*)&Xs4[kq2][m];
            #pragma unroll
            for (int n = 0; n < 32; n++) {
                ulonglong2 wq = *(const ulonglong2*)&Wp[n][kq2 * 4];
                acc2[n] = ffma2(wq.x, xq.x, acc2[n]);
                acc2[n] = ffma2(wq.y, xq.y, acc2[n]);
            }
        }

        #pragma unroll
        for (int n = 0; n < 32; n++) buf[n][m] = hadd2(acc2[n]);
        __syncthreads();
        {
            int n4 = t & 7, mg = t >> 3;
            #pragma unroll
            for (int s = 0; s < 8; s++) {
                int mr = s * 16 + mg;
                float4 o = make_float4(buf[n4 * 4 + 0][mr], buf[n4 * 4 + 1][mr],
                                       buf[n4 * 4 + 2][mr], buf[n4 * 4 + 3][mr]);
                ((float4*)g_Y)[(size_t)(m0 + mr) * 128 + n0 / 4 + pass * 8 + n4] = o;
            }
        }
        __syncthreads();
    }
}

// =====================================================================
// Kernel 2 (redesigned): direct-LDG z=Ax (coalesced, ILP-4, shfl reduce,
// x hoisted to registers), B + Y via cp.async overlapped with the A
// stream.  Smem ~19KB -> 12 blocks/SM (was 7).
// =====================================================================
#define GS_STRIDE 68

__global__ __launch_bounds__(128) void k2_setup(
    const float* __restrict__ Xg, const float* __restrict__ Ag,
    const float* __restrict__ Bg, const float* __restrict__ ccg,
    const float* __restrict__ dcg, const float* __restrict__ adg)
{
    __shared__ float xs [4][64];
    __shared__ float zs [4][64];
    __shared__ float gsm[4][NCON * GS_STRIDE];  // Y landing zone -> gradc
    __shared__ float Bsm[4][1024];              // B tile [64][16]
    __shared__ float Lgs[4][128];
    __shared__ float ccs[512];

    const int tid = threadIdx.x;
    const int w = tid >> 5, lane = tid & 31;
    const int b = blockIdx.x * 4 + w;

    for (int idx = tid; idx < 512; idx += 128) ccs[idx] = ccg[idx];

    if (lane < 16)
        *(float4*)&xs[w][lane * 4] = *(const float4*)(Xg + (size_t)b * 64 + lane * 4);

    // ---- issue B and Y cp.async groups up front (overlap with z=Ax) ----
    {
        const float* Bb = Bg + (size_t)b * 1024;
        #pragma unroll
        for (int it = 0; it < 8; it++) {
            int idx = it * 128 + lane * 4;
            cp_async16(&Bsm[w][idx], Bb + idx);
        }
        const float* Yb = g_Y + (size_t)b * 512;
        #pragma unroll
        for (int it = 0; it < 4; it++) {
            int idx = it * 128 + lane * 4;
            int m = idx >> 6, i = idx & 63;
            cp_async16(&gsm[w][m * GS_STRIDE + i], Yb + idx);
        }
        CP_COMMIT();
    }

    // ---- z = A x: direct coalesced LDG, x in registers ----
    {
        const float4* A4 = (const float4*)(Ag + (size_t)b * 4096);
        // x segment for this lane is constant: columns (lane&15)*4 ..+3
        float4 xv = *(const float4*)(Xg + (size_t)b * 64 + (lane & 15) * 4);
        const int rhalf = lane >> 4;   // which of the 2 rows per 32-float4 group
        #pragma unroll 2
        for (int g = 0; g < 8; g++) {
            float4 a[4];
            #pragma unroll
            for (int j = 0; j < 4; j++) a[j] = A4[(g * 4 + j) * 32 + lane];
            #pragma unroll
            for (int j = 0; j < 4; j++) {
                float part = fmaf(a[j].x, xv.x, a[j].y * xv.y);
                part = fmaf(a[j].z, xv.z, part);
                part = fmaf(a[j].w, xv.w, part);
                part += __shfl_xor_sync(0xffffffffu, part, 1);
                part += __shfl_xor_sync(0xffffffffu, part, 2);
                part += __shfl_xor_sync(0xffffffffu, part, 4);
                part += __shfl_xor_sync(0xffffffffu, part, 8);
                if ((lane & 15) == 0)
                    zs[w][(g * 4 + j) * 2 + rhalf] = part;
            }
        }
    }

    CP_WAIT(0);
    __syncthreads();   // ccs + xs visible; cp.async data visible

    // ---- gradc = Y + cc in place ----
    {
        #pragma unroll
        for (int it = 0; it < 4; it++) {
            int idx = it * 128 + lane * 4;
            int m = idx >> 6, i = idx & 63;
            float4 yv = *(float4*)&gsm[w][m * GS_STRIDE + i];
            yv.x += ccs[idx + 0]; yv.y += ccs[idx + 1];
            yv.z += ccs[idx + 2]; yv.w += ccs[idx + 3];
            *(float4*)&gsm[w][m * GS_STRIDE + i] = yv;
        }
    }
    __syncwarp();

    // dots: sa = x·gradc, sb = x·cc, sc = z·gradc
    float sa[NCON], sb[NCON], sc[NCON];
    {
        int i1 = lane, i2 = lane + 32;
        float x1 = xs[w][i1], x2 = xs[w][i2];
        float z1 = zs[w][i1], z2 = zs[w][i2];
        #pragma unroll
        for (int m = 0; m < NCON; m++) {
            float ga = gsm[w][m * GS_STRIDE + i1], gb2 = gsm[w][m * GS_STRIDE + i2];
            float ca = ccs[m * 64 + i1], cb = ccs[m * 64 + i2];
            sa[m] = fmaf(x2, gb2, x1 * ga);
            sb[m] = fmaf(x2, cb, x1 * ca);
            sc[m] = fmaf(z2, gb2, z1 * ga);
        }
    }
    #pragma unroll
    for (int off = 16; off; off >>= 1) {
        #pragma unroll
        for (int m = 0; m < NCON; m++) {
            sa[m] += __shfl_xor_sync(0xffffffffu, sa[m], off);
            sb[m] += __shfl_xor_sync(0xffffffffu, sb[m], off);
            sc[m] += __shfl_xor_sync(0xffffffffu, sc[m], off);
        }
    }

    // Lg[m][a] = -sum_i gradc[m][i] * B[i][a]
    {
        int m = lane >> 2, aq = lane & 3;
        float4 acc = make_float4(0.f, 0.f, 0.f, 0.f);
        const float4* B4 = (const float4*)&Bsm[w][0];
        #pragma unroll
        for (int i = 0; i < 64; i++) {
            float gv = gsm[w][m * GS_STRIDE + i];
            float4 bv = B4[i * 4 + aq];
            acc.x = fmaf(gv, bv.x, acc.x);
            acc.y = fmaf(gv, bv.y, acc.y);
            acc.z = fmaf(gv, bv.z, acc.z);
            acc.w = fmaf(gv, bv.w, acc.w);
        }
        acc.x = -acc.x; acc.y = -acc.y; acc.z = -acc.z; acc.w = -acc.w;
        *(float4*)&Lgs[w][m * 16 + aq * 4] = acc;
        *(float4*)(g_Lg + (size_t)b * 128 + m * 16 + aq * 4) = acc;
    }
    __syncwarp();

    if (lane < NCON) {
        int m = lane;
        float g    = 0.5f * sa[m] + 0.5f * sb[m] - dcg[m];
        float bvec = sc[m] + g;
        float qm = bvec;
        const float* ad = adg + (size_t)b * 16;
        #pragma unroll
        for (int a = 0; a < 16; a++) qm = fmaf(-Lgs[w][m * 16 + a], ad[a], qm);
        g_q[(size_t)b * 8 + m] = qm;
    }

    #pragma unroll
    for (int e = 0; e < 2; e++) {
        int idx = lane + e * 32;
        int r = idx >> 3, cI = idx & 7;
        float s = 0.f;
        #pragma unroll
        for (int a = 0; a < 16; a++) s = fmaf(Lgs[w][r * 16 + a], Lgs[w][cI * 16 + a], s);
        g_S[(size_t)b * 64 + idx] = 0.5f * s;
    }
}

// =====================================================================
// Kernel 3: unchanged from R8 (POW 16 + FISTA 100; frozen).
// =====================================================================
__global__ __launch_bounds__(128) void k3_fista(const float* __restrict__ adg,
                                                float* __restrict__ out, int batch)
{
    int b = blockIdx.x * 128 + threadIdx.x;
    if (b >= batch) return;

    ull Sp[32];
    {
        const ulonglong2* S2 = (const ulonglong2*)(g_S + (size_t)b * 64);
        #pragma unroll
        for (int i = 0; i < 16; i++) {
            ulonglong2 v = S2[i];
            Sp[2 * i] = v.x; Sp[2 * i + 1] = v.y;
        }
    }
    float q[8];
    {
        const float4* q4 = (const float4*)(g_q + (size_t)b * 8);
        float4 a0 = q4[0], a1 = q4[1];
        q[0] = a0.x; q[1] = a0.y; q[2] = a0.z; q[3] = a0.w;
        q[4] = a1.x; q[5] = a1.y; q[6] = a1.z; q[7] = a1.w;
    }

    float v[8];
    #pragma unroll
    for (int k = 0; k < 8; k++) v[k] = 1.0f + 0.0625f * (float)k;
    #pragma unroll 1
    for (int it = 0; it < POW_ITERS; it++) {
        ull vp[4];
        #pragma unroll
        for (int j = 0; j < 4; j++) vp[j] = pack2(v[2 * j], v[2 * j + 1]);
        float wv[8];
        #pragma unroll
        for (int k = 0; k < 8; k++) wv[k] = dot8p(Sp + 4 * k, vp);
        float ss = 1e-30f;
        #pragma unroll
        for (int k = 0; k < 8; k++) ss = fmaf(wv[k], wv[k], ss);
        float inv = rsqrtf(ss);
        #pragma unroll
        for (int k = 0; k < 8; k++) v[k] = wv[k] * inv;
    }
    float num = 0.f, den = 1e-30f;
    {
        ull vp[4];
        #pragma unroll
        for (int j = 0; j < 4; j++) vp[j] = pack2(v[2 * j], v[2 * j + 1]);
        #pragma unroll
        for (int k = 0; k < 8; k++) {
            num = fmaf(v[k], dot8p(Sp + 4 * k, vp), num);
            den = fmaf(v[k], v[k], den);
        }
    }
    float mu = fmaxf(num / den, 0.f);
    float lamMax = EPSC + 0.5f * (mu + sqrtf(fmaf(mu, mu, 4.f * EPSC * EPSC)));
    float L = lamMax * 1.01f + 1e-6f;
    float t = 1.0f / L;

    float lam[16], y[16];
    #pragma unroll
    for (int k = 0; k < 16; k++) { lam[k] = 0.f; y[k] = 0.f; }
    float tk = 1.0f;
    #pragma unroll 1
    for (int it = 0; it < N_ITERS; it++) {
        ull yp[4];
        #pragma unroll
        for (int j = 0; j < 4; j++) yp[j] = pack2(y[2 * j], y[2 * j + 1]);
        float wv[8];
        #pragma unroll
        for (int k = 0; k < 8; k++) wv[k] = dot8p(Sp + 4 * k, yp);
        float tk1 = 0.5f * (1.0f + sqrtf(fmaf(4.0f * tk, tk, 1.0f)));
        float beta = (tk - 1.0f) / tk1;
        #pragma unroll
        for (int k = 0; k < 8; k++) {
            float e  = EPSC * (y[k] + y[k + 8]);
            float gt = wv[k] + e - q[k];
            float lt = fmaxf(fmaf(-t, gt, y[k]), 0.f);
            float lb = fmaxf(fmaf(-t, e, y[k + 8]), 0.f);
            y[k]     = fmaf(beta, lt - lam[k], lt);
            y[k + 8] = fmaf(beta, lb - lam[k + 8], lb);
            lam[k] = lt; lam[k + 8] = lb;
        }
        tk = tk1;
    }

    float a[16];
    {
        const float4* ad4 = (const float4*)(adg + (size_t)b * 16);
        #pragma unroll
        for (int i = 0; i < 4; i++) {
            float4 t4 = ad4[i];
            a[i * 4 + 0] = t4.x; a[i * 4 + 1] = t4.y; a[i * 4 + 2] = t4.z; a[i * 4 + 3] = t4.w;
        }
        const float* Lgb = g_Lg + (size_t)b * 128;
        #pragma unroll
        for (int m = 0; m < 8; m++) {
            float lm = 0.5f * lam[m];
            #pragma unroll
            for (int j = 0; j < 16; j++) a[j] = fmaf(lm, Lgb[m * 16 + j], a[j]);
        }
    }
    float4* o4 = (float4*)(out + (size_t)b * 16);
    #pragma unroll
    for (int i = 0; i < 4; i++)
        o4[i] = make_float4(a[i * 4 + 0], a[i * 4 + 1], a[i * 4 + 2], a[i * 4 + 3]);
}

// =====================================================================
extern "C" void kernel_launch(void* const* d_in, const int* in_sizes, int n_in,
                              void* d_out, int out_size)
{
    const float* a_des = (const float*)d_in[0];
    const float* x     = (const float*)d_in[1];
    const float* A     = (const float*)d_in[2];
    const float* B     = (const float*)d_in[3];
    const float* Qc    = (const float*)d_in[4];
    const float* cc    = (const float*)d_in[5];
    const float* dc    = (const float*)d_in[6];
    const int batch = in_sizes[0] / ADIM;   // 16384

    cudaFuncSetAttribute(k1_gemm, cudaFuncAttributeMaxDynamicSharedMemorySize, K1_SMEM);

    dim3 g1(batch / 128, 512 / 64);
    k1_gemm<<<g1, 128, K1_SMEM>>>(x, Qc);
    k2_setup<<<batch / 4, 128>>>(x, A, B, cc, dc, a_des);
    k3_fista<<<(batch + 127) / 128, 128>>>(a_des, (float*)d_out, batch);
}